// round 1
// baseline (speedup 1.0000x reference)
#include <cuda_runtime.h>
#include <math.h>

#define NN 50000
#define NE 800000
#define FIN 128
#define C1  256     // H1*HID
#define H1  8
#define HID 32
#define C2  40

// ---------------- scratch (static device globals; no allocation) ----------------
__device__ float g_z1[NN * C1];     // layer1 projected features [N,256]
__device__ float g_h [NN * C1];     // elu(layer1 output) [N,256]
__device__ float g_el1[NN * H1];
__device__ float g_er1[NN * H1];
__device__ float g_z2[NN * C2];     // layer2 projected [N,40]
__device__ float g_el2[NN];
__device__ float g_er2[NN];
__device__ int   g_deg[NN];
__device__ int   g_off[NN + 1];
__device__ int   g_cur[NN];
__device__ int   g_csr[NE];         // src ids grouped by dst

// ---------------- CSR build ----------------
__global__ void k_zero_deg() {
    int i = blockIdx.x * blockDim.x + threadIdx.x;
    if (i < NN) g_deg[i] = 0;
}

__global__ void k_hist(const int* __restrict__ dst) {
    int i = blockIdx.x * blockDim.x + threadIdx.x;
    if (i < NE) atomicAdd(&g_deg[dst[i]], 1);
}

__global__ void k_scan() {
    __shared__ int sdata[1024];
    int t = threadIdx.x;
    const int CH = (NN + 1023) / 1024;  // 49
    int start = t * CH;
    int end   = start + CH; if (end > NN) end = NN;
    int s = 0;
    for (int i = start; i < end && i < NN; i++) s += g_deg[i];
    sdata[t] = s;
    __syncthreads();
    // Hillis-Steele inclusive scan
    for (int off = 1; off < 1024; off <<= 1) {
        int v = 0;
        if (t >= off) v = sdata[t - off];
        __syncthreads();
        if (t >= off) sdata[t] += v;
        __syncthreads();
    }
    int run = sdata[t] - s;  // exclusive prefix
    for (int i = start; i < end && i < NN; i++) {
        g_off[i] = run;
        g_cur[i] = run;
        run += g_deg[i];
    }
    if (t == 1023) g_off[NN] = sdata[1023];
}

__global__ void k_scatter(const int* __restrict__ src, const int* __restrict__ dst) {
    int i = blockIdx.x * blockDim.x + threadIdx.x;
    if (i < NE) {
        int pos = atomicAdd(&g_cur[dst[i]], 1);
        g_csr[pos] = src[i];
    }
}

// ---------------- GEMM1: z1[N,256] = feat[N,128] @ W1[128,256] ----------------
// BM=128 BN=128 BK=8, 256 threads, 8x8 microtile
__global__ void k_gemm1(const float* __restrict__ A, const float* __restrict__ B) {
    __shared__ float As[8][128];
    __shared__ float Bs[8][128];
    const int K = 128, N = 256;
    int bx = blockIdx.x;         // 0..1 (N tiles)
    int by = blockIdx.y;         // M tiles
    int tid = threadIdx.x;
    int tx = tid & 15;           // col group
    int ty = tid >> 4;           // row group
    float acc[8][8];
#pragma unroll
    for (int i = 0; i < 8; i++)
#pragma unroll
        for (int j = 0; j < 8; j++) acc[i][j] = 0.f;

    int aRow = by * 128 + (tid >> 1);
    int aCol = (tid & 1) * 4;
    int bRow = tid >> 5;
    int bCol = bx * 128 + (tid & 31) * 4;

    for (int k0 = 0; k0 < K; k0 += 8) {
        float4 av = make_float4(0.f, 0.f, 0.f, 0.f);
        if (aRow < NN) av = *(const float4*)(A + aRow * K + k0 + aCol);
        As[aCol + 0][tid >> 1] = av.x;
        As[aCol + 1][tid >> 1] = av.y;
        As[aCol + 2][tid >> 1] = av.z;
        As[aCol + 3][tid >> 1] = av.w;
        float4 bv = *(const float4*)(B + (k0 + bRow) * N + bCol);
        *(float4*)&Bs[bRow][(tid & 31) * 4] = bv;
        __syncthreads();
#pragma unroll
        for (int k = 0; k < 8; k++) {
            float af[8], bf[8];
#pragma unroll
            for (int i = 0; i < 8; i++) af[i] = As[k][ty * 8 + i];
#pragma unroll
            for (int j = 0; j < 8; j++) bf[j] = Bs[k][tx * 8 + j];
#pragma unroll
            for (int i = 0; i < 8; i++)
#pragma unroll
                for (int j = 0; j < 8; j++) acc[i][j] += af[i] * bf[j];
        }
        __syncthreads();
    }
#pragma unroll
    for (int i = 0; i < 8; i++) {
        int row = by * 128 + ty * 8 + i;
        if (row < NN) {
            float4* cp = (float4*)(g_z1 + row * 256 + bx * 128 + tx * 8);
            cp[0] = make_float4(acc[i][0], acc[i][1], acc[i][2], acc[i][3]);
            cp[1] = make_float4(acc[i][4], acc[i][5], acc[i][6], acc[i][7]);
        }
    }
}

// ---------------- el1/er1: per node, per head dot with al1/ar1 ----------------
__global__ void k_eler1(const float* __restrict__ al1, const float* __restrict__ ar1) {
    int n = blockIdx.x * 8 + (threadIdx.x >> 5);
    if (n >= NN) return;
    int lane = threadIdx.x & 31;
    const float4* zp = (const float4*)(g_z1 + n * 256);
    float4 a = zp[2 * lane];
    float4 b = zp[2 * lane + 1];
    const float4* alp = (const float4*)(al1);
    const float4* arp = (const float4*)(ar1);
    float4 la = alp[2 * lane], lb = alp[2 * lane + 1];
    float4 ra = arp[2 * lane], rb = arp[2 * lane + 1];
    float pel = a.x * la.x + a.y * la.y + a.z * la.z + a.w * la.w
              + b.x * lb.x + b.y * lb.y + b.z * lb.z + b.w * lb.w;
    float per = a.x * ra.x + a.y * ra.y + a.z * ra.z + a.w * ra.w
              + b.x * rb.x + b.y * rb.y + b.z * rb.z + b.w * rb.w;
    // reduce over groups of 4 lanes (one head per group)
    pel += __shfl_xor_sync(0xffffffffu, pel, 1);
    per += __shfl_xor_sync(0xffffffffu, per, 1);
    pel += __shfl_xor_sync(0xffffffffu, pel, 2);
    per += __shfl_xor_sync(0xffffffffu, per, 2);
    if ((lane & 3) == 0) {
        int h = lane >> 2;
        g_el1[n * 8 + h] = pel;
        g_er1[n * 8 + h] = per;
    }
}

__device__ __forceinline__ float lrelu(float x) { return x > 0.f ? x : 0.2f * x; }
__device__ __forceinline__ float elu(float x)  { return x > 0.f ? x : __expf(x) - 1.f; }

// ---------------- layer1 aggregation: warp per dst node, fused softmax ----------------
__global__ void k_agg1(const float* __restrict__ b1) {
    int n = blockIdx.x * 8 + (threadIdx.x >> 5);
    if (n >= NN) return;
    int lane = threadIdx.x & 31;
    int beg = g_off[n], end = g_off[n + 1];
    int h0 = lane >> 3;        // head of channels [4*lane, 4*lane+4)
    int h1 = 4 + h0;           // head of channels [128+4*lane, ...)
    float erd0 = g_er1[n * 8 + h0];
    float erd1 = g_er1[n * 8 + h1];
    float4 acc0 = make_float4(0.f, 0.f, 0.f, 0.f);
    float4 acc1 = make_float4(0.f, 0.f, 0.f, 0.f);
    float ds0 = 0.f, ds1 = 0.f;
    for (int j = beg; j < end; j++) {
        int s = __ldg(&g_csr[j]);
        float e0 = lrelu(g_el1[s * 8 + h0] + erd0);
        float e1 = lrelu(g_el1[s * 8 + h1] + erd1);
        float x0 = __expf(e0);
        float x1 = __expf(e1);
        ds0 += x0; ds1 += x1;
        const float4* zp = (const float4*)(g_z1 + s * 256);
        float4 a = __ldg(&zp[lane]);
        float4 b = __ldg(&zp[32 + lane]);
        acc0.x += x0 * a.x; acc0.y += x0 * a.y; acc0.z += x0 * a.z; acc0.w += x0 * a.w;
        acc1.x += x1 * b.x; acc1.y += x1 * b.y; acc1.z += x1 * b.z; acc1.w += x1 * b.w;
    }
    float inv0 = (end > beg) ? 1.f / ds0 : 0.f;
    float inv1 = (end > beg) ? 1.f / ds1 : 0.f;
    float4 bb0 = *(const float4*)(b1 + 4 * lane);
    float4 bb1 = *(const float4*)(b1 + 128 + 4 * lane);
    float4 o0, o1;
    o0.x = elu(acc0.x * inv0 + bb0.x); o0.y = elu(acc0.y * inv0 + bb0.y);
    o0.z = elu(acc0.z * inv0 + bb0.z); o0.w = elu(acc0.w * inv0 + bb0.w);
    o1.x = elu(acc1.x * inv1 + bb1.x); o1.y = elu(acc1.y * inv1 + bb1.y);
    o1.z = elu(acc1.z * inv1 + bb1.z); o1.w = elu(acc1.w * inv1 + bb1.w);
    float4* hp = (float4*)(g_h + n * 256);
    hp[lane] = o0;
    hp[32 + lane] = o1;
}

// ---------------- GEMM2: z2[N,40] = h[N,256] @ W2[256,40] ----------------
// BM=64, full N=40, 128 threads, 4x5 microtile, W2 fully in smem
__global__ void k_gemm2(const float* __restrict__ W2) {
    __shared__ float Bs[256 * 40];       // 40 KB
    __shared__ float As[16][64];         // 4 KB
    int by = blockIdx.x;
    int tid = threadIdx.x;               // 128
    int tx = tid & 7;                    // col group (5 cols)
    int ty = tid >> 3;                   // row group (4 rows)

    // load W2 into smem (10240 floats = 2560 float4)
    {
        const float4* wp = (const float4*)W2;
        float4* bp = (float4*)Bs;
        for (int i = tid; i < 2560; i += 128) bp[i] = wp[i];
    }
    float acc[4][5];
#pragma unroll
    for (int i = 0; i < 4; i++)
#pragma unroll
        for (int j = 0; j < 5; j++) acc[i][j] = 0.f;

    for (int k0 = 0; k0 < 256; k0 += 16) {
        __syncthreads();
        // load A tile: 64 rows x 16 k = 256 float4
        for (int q = 0; q < 2; q++) {
            int li = tid + q * 128;              // 0..255
            int row = li >> 2;
            int ck  = (li & 3) * 4;
            int grow = by * 64 + row;
            float4 v = make_float4(0.f, 0.f, 0.f, 0.f);
            if (grow < NN) v = *(const float4*)(g_h + grow * 256 + k0 + ck);
            As[ck + 0][row] = v.x;
            As[ck + 1][row] = v.y;
            As[ck + 2][row] = v.z;
            As[ck + 3][row] = v.w;
        }
        __syncthreads();
#pragma unroll
        for (int kk = 0; kk < 16; kk++) {
            float af[4], bf[5];
#pragma unroll
            for (int i = 0; i < 4; i++) af[i] = As[kk][ty * 4 + i];
#pragma unroll
            for (int j = 0; j < 5; j++) bf[j] = Bs[(k0 + kk) * 40 + tx * 5 + j];
#pragma unroll
            for (int i = 0; i < 4; i++)
#pragma unroll
                for (int j = 0; j < 5; j++) acc[i][j] += af[i] * bf[j];
        }
    }
#pragma unroll
    for (int i = 0; i < 4; i++) {
        int row = by * 64 + ty * 4 + i;
        if (row < NN) {
#pragma unroll
            for (int j = 0; j < 5; j++) g_z2[row * 40 + tx * 5 + j] = acc[i][j];
        }
    }
}

// ---------------- el2/er2 ----------------
__global__ void k_eler2(const float* __restrict__ al2, const float* __restrict__ ar2) {
    int n = blockIdx.x * 8 + (threadIdx.x >> 5);
    if (n >= NN) return;
    int lane = threadIdx.x & 31;
    float v0 = g_z2[n * 40 + lane];
    float pel = v0 * __ldg(al2 + lane);
    float per = v0 * __ldg(ar2 + lane);
    if (lane < 8) {
        float v1 = g_z2[n * 40 + 32 + lane];
        pel += v1 * __ldg(al2 + 32 + lane);
        per += v1 * __ldg(ar2 + 32 + lane);
    }
#pragma unroll
    for (int off = 16; off > 0; off >>= 1) {
        pel += __shfl_xor_sync(0xffffffffu, pel, off);
        per += __shfl_xor_sync(0xffffffffu, per, off);
    }
    if (lane == 0) { g_el2[n] = pel; g_er2[n] = per; }
}

// ---------------- layer2 aggregation: warp per dst node ----------------
__global__ void k_agg2(const float* __restrict__ b2, float* __restrict__ out) {
    int n = blockIdx.x * 8 + (threadIdx.x >> 5);
    if (n >= NN) return;
    int lane = threadIdx.x & 31;
    int beg = g_off[n], end = g_off[n + 1];
    float erd = g_er2[n];
    float acc0 = 0.f, acc1 = 0.f, ds = 0.f;
    for (int j = beg; j < end; j++) {
        int s = __ldg(&g_csr[j]);
        float e = lrelu(g_el2[s] + erd);
        float x = __expf(e);
        ds += x;
        acc0 += x * __ldg(&g_z2[s * 40 + lane]);
        if (lane < 8) acc1 += x * __ldg(&g_z2[s * 40 + 32 + lane]);
    }
    float inv = (end > beg) ? 1.f / ds : 0.f;
    out[n * 40 + lane] = acc0 * inv + __ldg(b2 + lane);
    if (lane < 8) out[n * 40 + 32 + lane] = acc1 * inv + __ldg(b2 + 32 + lane);
}

// ---------------- launch ----------------
extern "C" void kernel_launch(void* const* d_in, const int* in_sizes, int n_in,
                              void* d_out, int out_size) {
    const float* feat = (const float*)d_in[0];
    const int*   src  = (const int*)d_in[1];
    const int*   dst  = (const int*)d_in[2];
    const float* W1   = (const float*)d_in[3];
    const float* al1  = (const float*)d_in[4];
    const float* ar1  = (const float*)d_in[5];
    const float* b1   = (const float*)d_in[6];
    const float* W2   = (const float*)d_in[7];
    const float* al2  = (const float*)d_in[8];
    const float* ar2  = (const float*)d_in[9];
    const float* b2   = (const float*)d_in[10];
    float* out = (float*)d_out;

    // CSR build
    k_zero_deg<<<(NN + 255) / 256, 256>>>();
    k_hist<<<(NE + 255) / 256, 256>>>(dst);
    k_scan<<<1, 1024>>>();
    k_scatter<<<(NE + 255) / 256, 256>>>(src, dst);

    // layer 1
    dim3 g1(2, (NN + 127) / 128);
    k_gemm1<<<g1, 256>>>(feat, W1);
    k_eler1<<<(NN + 7) / 8, 256>>>(al1, ar1);
    k_agg1<<<(NN + 7) / 8, 256>>>(b1);

    // layer 2
    k_gemm2<<<(NN + 63) / 64, 128>>>(W2);
    k_eler2<<<(NN + 7) / 8, 256>>>(al2, ar2);
    k_agg2<<<(NN + 7) / 8, 256>>>(b2, out);
}

// round 2
// speedup vs baseline: 1.3770x; 1.3770x over previous
#include <cuda_runtime.h>
#include <math.h>

#define NN 50000
#define NE 800000
#define FIN 128
#define C1  256
#define H1  8
#define HID 32
#define C2  40
#define NB  196   // (NN+255)/256

// ---------------- scratch ----------------
__device__ float g_z1[NN * C1];
__device__ float g_h [NN * C1];
__device__ float g_el1[NN * H1];
__device__ float g_er1[NN * H1];
__device__ float g_z2[NN * C2];
__device__ float g_el2[NN];
__device__ float g_er2[NN];
__device__ int   g_deg[NN];
__device__ int   g_off[NN + 1];
__device__ int   g_cur[NN];
__device__ int   g_csr[NE];
__device__ int   g_bsum[NB];

// ---------------- CSR build ----------------
__global__ void k_zero_deg() {
    int i = blockIdx.x * blockDim.x + threadIdx.x;
    if (i < NN) g_deg[i] = 0;
}

__global__ void k_hist(const int* __restrict__ dst) {
    int i = blockIdx.x * blockDim.x + threadIdx.x;
    if (i < NE) atomicAdd(&g_deg[dst[i]], 1);
}

// phase A: per-block sums of 256 degrees
__global__ void k_scanA() {
    __shared__ int sd[256];
    int t = threadIdx.x;
    int i = blockIdx.x * 256 + t;
    sd[t] = (i < NN) ? g_deg[i] : 0;
    __syncthreads();
    for (int off = 128; off > 0; off >>= 1) {
        if (t < off) sd[t] += sd[t + off];
        __syncthreads();
    }
    if (t == 0) g_bsum[blockIdx.x] = sd[0];
}

// phase B: exclusive scan of block sums (single block)
__global__ void k_scanB() {
    __shared__ int sd[256];
    int t = threadIdx.x;
    int v = (t < NB) ? g_bsum[t] : 0;
    sd[t] = v;
    __syncthreads();
    for (int off = 1; off < 256; off <<= 1) {
        int u = 0;
        if (t >= off) u = sd[t - off];
        __syncthreads();
        if (t >= off) sd[t] += u;
        __syncthreads();
    }
    if (t < NB) g_bsum[t] = sd[t] - v;     // exclusive
    if (t == 255) g_off[NN] = sd[255];     // total
}

// phase C: local exclusive scan + base -> g_off / g_cur
__global__ void k_scanC() {
    __shared__ int sd[256];
    int t = threadIdx.x;
    int i = blockIdx.x * 256 + t;
    int v = (i < NN) ? g_deg[i] : 0;
    sd[t] = v;
    __syncthreads();
    for (int off = 1; off < 256; off <<= 1) {
        int u = 0;
        if (t >= off) u = sd[t - off];
        __syncthreads();
        if (t >= off) sd[t] += u;
        __syncthreads();
    }
    if (i < NN) {
        int ex = g_bsum[blockIdx.x] + sd[t] - v;
        g_off[i] = ex;
        g_cur[i] = ex;
    }
}

__global__ void k_scatter(const int* __restrict__ src, const int* __restrict__ dst) {
    int i = blockIdx.x * blockDim.x + threadIdx.x;
    if (i < NE) {
        int pos = atomicAdd(&g_cur[dst[i]], 1);
        g_csr[pos] = src[i];
    }
}

// ---------------- GEMM1 + fused el1/er1 ----------------
// z1[N,256] = feat[N,128] @ W1[128,256];  BM=64 BN=256 BK=8, 256 thr, 8x8 micro
__global__ void k_gemm1(const float* __restrict__ A, const float* __restrict__ B,
                        const float* __restrict__ al1, const float* __restrict__ ar1) {
    __shared__ float As[8][64];
    __shared__ float Bs[8][256];
    const int K = 128;
    int by = blockIdx.x;
    int tid = threadIdx.x;
    int tx = tid & 31;           // col group: cols tx*8..tx*8+7 (head = tx>>2)
    int ty = tid >> 5;           // row group: rows ty*8..ty*8+7
    float acc[8][8];
#pragma unroll
    for (int i = 0; i < 8; i++)
#pragma unroll
        for (int j = 0; j < 8; j++) acc[i][j] = 0.f;

    int aRow = by * 64 + (tid >> 1);
    int aCol = (tid & 1) * 4;
    int bRow = tid >> 5;
    int bCol = (tid & 31) * 4;

    for (int k0 = 0; k0 < K; k0 += 8) {
        if (tid < 128) {
            float4 av = make_float4(0.f, 0.f, 0.f, 0.f);
            if (aRow < NN) av = *(const float4*)(A + aRow * K + k0 + aCol);
            As[aCol + 0][tid >> 1] = av.x;
            As[aCol + 1][tid >> 1] = av.y;
            As[aCol + 2][tid >> 1] = av.z;
            As[aCol + 3][tid >> 1] = av.w;
        }
        float4 bv0 = *(const float4*)(B + (k0 + bRow) * C1 + bCol);
        float4 bv1 = *(const float4*)(B + (k0 + bRow) * C1 + bCol + 128);
        *(float4*)&Bs[bRow][bCol] = bv0;
        *(float4*)&Bs[bRow][bCol + 128] = bv1;
        __syncthreads();
#pragma unroll
        for (int k = 0; k < 8; k++) {
            float4 a0 = *(float4*)&As[k][ty * 8];
            float4 a1 = *(float4*)&As[k][ty * 8 + 4];
            float4 b0 = *(float4*)&Bs[k][tx * 8];
            float4 b1 = *(float4*)&Bs[k][tx * 8 + 4];
            float af[8] = {a0.x, a0.y, a0.z, a0.w, a1.x, a1.y, a1.z, a1.w};
            float bf[8] = {b0.x, b0.y, b0.z, b0.w, b1.x, b1.y, b1.z, b1.w};
#pragma unroll
            for (int i = 0; i < 8; i++)
#pragma unroll
                for (int j = 0; j < 8; j++) acc[i][j] += af[i] * bf[j];
        }
        __syncthreads();
    }

    // epilogue: write z1 + fused attention dots
    float alv[8], arv[8];
#pragma unroll
    for (int j = 0; j < 8; j++) {
        alv[j] = __ldg(al1 + tx * 8 + j);
        arv[j] = __ldg(ar1 + tx * 8 + j);
    }
    int h = tx >> 2;
#pragma unroll
    for (int i = 0; i < 8; i++) {
        int row = by * 64 + ty * 8 + i;
        float pel = 0.f, per = 0.f;
#pragma unroll
        for (int j = 0; j < 8; j++) {
            pel += acc[i][j] * alv[j];
            per += acc[i][j] * arv[j];
        }
        pel += __shfl_xor_sync(0xffffffffu, pel, 1);
        per += __shfl_xor_sync(0xffffffffu, per, 1);
        pel += __shfl_xor_sync(0xffffffffu, pel, 2);
        per += __shfl_xor_sync(0xffffffffu, per, 2);
        if (row < NN) {
            float4* cp = (float4*)(g_z1 + row * 256 + tx * 8);
            cp[0] = make_float4(acc[i][0], acc[i][1], acc[i][2], acc[i][3]);
            cp[1] = make_float4(acc[i][4], acc[i][5], acc[i][6], acc[i][7]);
            if ((tx & 3) == 0) {
                g_el1[row * 8 + h] = pel;
                g_er1[row * 8 + h] = per;
            }
        }
    }
}

__device__ __forceinline__ float lrelu(float x) { return x > 0.f ? x : 0.2f * x; }
__device__ __forceinline__ float elu(float x)  { return x > 0.f ? x : __expf(x) - 1.f; }

// ---------------- layer1 aggregation (warp/node, unroll-2) ----------------
__global__ void k_agg1(const float* __restrict__ b1) {
    int n = blockIdx.x * 8 + (threadIdx.x >> 5);
    if (n >= NN) return;
    int lane = threadIdx.x & 31;
    int beg = g_off[n], end = g_off[n + 1];
    int h0 = lane >> 3;
    int h1 = 4 + h0;
    float erd0 = g_er1[n * 8 + h0];
    float erd1 = g_er1[n * 8 + h1];
    float4 acc0 = make_float4(0.f, 0.f, 0.f, 0.f);
    float4 acc1 = make_float4(0.f, 0.f, 0.f, 0.f);
    float ds0 = 0.f, ds1 = 0.f;
    int j = beg;
    for (; j + 2 <= end; j += 2) {
        int s0 = __ldg(&g_csr[j]);
        int s1 = __ldg(&g_csr[j + 1]);
        float ea0 = __ldg(&g_el1[s0 * 8 + h0]);
        float eb0 = __ldg(&g_el1[s0 * 8 + h1]);
        float ea1 = __ldg(&g_el1[s1 * 8 + h0]);
        float eb1 = __ldg(&g_el1[s1 * 8 + h1]);
        const float4* zp0 = (const float4*)(g_z1 + s0 * 256);
        const float4* zp1 = (const float4*)(g_z1 + s1 * 256);
        float4 a0 = __ldg(&zp0[lane]);
        float4 c0 = __ldg(&zp0[32 + lane]);
        float4 a1 = __ldg(&zp1[lane]);
        float4 c1 = __ldg(&zp1[32 + lane]);
        float x00 = __expf(lrelu(ea0 + erd0));
        float x01 = __expf(lrelu(eb0 + erd1));
        float x10 = __expf(lrelu(ea1 + erd0));
        float x11 = __expf(lrelu(eb1 + erd1));
        ds0 += x00 + x10;
        ds1 += x01 + x11;
        acc0.x += x00 * a0.x + x10 * a1.x;
        acc0.y += x00 * a0.y + x10 * a1.y;
        acc0.z += x00 * a0.z + x10 * a1.z;
        acc0.w += x00 * a0.w + x10 * a1.w;
        acc1.x += x01 * c0.x + x11 * c1.x;
        acc1.y += x01 * c0.y + x11 * c1.y;
        acc1.z += x01 * c0.z + x11 * c1.z;
        acc1.w += x01 * c0.w + x11 * c1.w;
    }
    if (j < end) {
        int s = __ldg(&g_csr[j]);
        float e0 = lrelu(__ldg(&g_el1[s * 8 + h0]) + erd0);
        float e1 = lrelu(__ldg(&g_el1[s * 8 + h1]) + erd1);
        float x0 = __expf(e0);
        float x1 = __expf(e1);
        ds0 += x0; ds1 += x1;
        const float4* zp = (const float4*)(g_z1 + s * 256);
        float4 a = __ldg(&zp[lane]);
        float4 b = __ldg(&zp[32 + lane]);
        acc0.x += x0 * a.x; acc0.y += x0 * a.y; acc0.z += x0 * a.z; acc0.w += x0 * a.w;
        acc1.x += x1 * b.x; acc1.y += x1 * b.y; acc1.z += x1 * b.z; acc1.w += x1 * b.w;
    }
    float inv0 = (end > beg) ? 1.f / ds0 : 0.f;
    float inv1 = (end > beg) ? 1.f / ds1 : 0.f;
    float4 bb0 = *(const float4*)(b1 + 4 * lane);
    float4 bb1 = *(const float4*)(b1 + 128 + 4 * lane);
    float4 o0, o1;
    o0.x = elu(acc0.x * inv0 + bb0.x); o0.y = elu(acc0.y * inv0 + bb0.y);
    o0.z = elu(acc0.z * inv0 + bb0.z); o0.w = elu(acc0.w * inv0 + bb0.w);
    o1.x = elu(acc1.x * inv1 + bb1.x); o1.y = elu(acc1.y * inv1 + bb1.y);
    o1.z = elu(acc1.z * inv1 + bb1.z); o1.w = elu(acc1.w * inv1 + bb1.w);
    float4* hp = (float4*)(g_h + n * 256);
    hp[lane] = o0;
    hp[32 + lane] = o1;
}

// ---------------- GEMM2 + fused el2/er2 ----------------
__global__ void k_gemm2(const float* __restrict__ W2,
                        const float* __restrict__ al2, const float* __restrict__ ar2) {
    __shared__ float Bs[256 * 40];
    __shared__ float As[16][64];
    int by = blockIdx.x;
    int tid = threadIdx.x;
    int tx = tid & 7;
    int ty = tid >> 3;
    {
        const float4* wp = (const float4*)W2;
        float4* bp = (float4*)Bs;
        for (int i = tid; i < 2560; i += 128) bp[i] = wp[i];
    }
    float acc[4][5];
#pragma unroll
    for (int i = 0; i < 4; i++)
#pragma unroll
        for (int j = 0; j < 5; j++) acc[i][j] = 0.f;

    for (int k0 = 0; k0 < 256; k0 += 16) {
        __syncthreads();
        for (int q = 0; q < 2; q++) {
            int li = tid + q * 128;
            int row = li >> 2;
            int ck  = (li & 3) * 4;
            int grow = by * 64 + row;
            float4 v = make_float4(0.f, 0.f, 0.f, 0.f);
            if (grow < NN) v = *(const float4*)(g_h + grow * 256 + k0 + ck);
            As[ck + 0][row] = v.x;
            As[ck + 1][row] = v.y;
            As[ck + 2][row] = v.z;
            As[ck + 3][row] = v.w;
        }
        __syncthreads();
#pragma unroll
        for (int kk = 0; kk < 16; kk++) {
            float af[4], bf[5];
#pragma unroll
            for (int i = 0; i < 4; i++) af[i] = As[kk][ty * 4 + i];
#pragma unroll
            for (int j = 0; j < 5; j++) bf[j] = Bs[(k0 + kk) * 40 + tx * 5 + j];
#pragma unroll
            for (int i = 0; i < 4; i++)
#pragma unroll
                for (int j = 0; j < 5; j++) acc[i][j] += af[i] * bf[j];
        }
    }
    float alv[5], arv[5];
#pragma unroll
    for (int j = 0; j < 5; j++) {
        alv[j] = __ldg(al2 + tx * 5 + j);
        arv[j] = __ldg(ar2 + tx * 5 + j);
    }
#pragma unroll
    for (int i = 0; i < 4; i++) {
        int row = by * 64 + ty * 4 + i;
        float pel = 0.f, per = 0.f;
#pragma unroll
        for (int j = 0; j < 5; j++) {
            pel += acc[i][j] * alv[j];
            per += acc[i][j] * arv[j];
        }
        pel += __shfl_xor_sync(0xffffffffu, pel, 1);
        per += __shfl_xor_sync(0xffffffffu, per, 1);
        pel += __shfl_xor_sync(0xffffffffu, pel, 2);
        per += __shfl_xor_sync(0xffffffffu, per, 2);
        pel += __shfl_xor_sync(0xffffffffu, pel, 4);
        per += __shfl_xor_sync(0xffffffffu, per, 4);
        if (row < NN) {
#pragma unroll
            for (int j = 0; j < 5; j++) g_z2[row * 40 + tx * 5 + j] = acc[i][j];
            if (tx == 0) {
                g_el2[row] = pel;
                g_er2[row] = per;
            }
        }
    }
}

// ---------------- layer2 aggregation (warp/node, unroll-2) ----------------
__global__ void k_agg2(const float* __restrict__ b2, float* __restrict__ out) {
    int n = blockIdx.x * 8 + (threadIdx.x >> 5);
    if (n >= NN) return;
    int lane = threadIdx.x & 31;
    int beg = g_off[n], end = g_off[n + 1];
    float erd = g_er2[n];
    float acc0 = 0.f, acc1 = 0.f, ds = 0.f;
    int j = beg;
    for (; j + 2 <= end; j += 2) {
        int s0 = __ldg(&g_csr[j]);
        int s1 = __ldg(&g_csr[j + 1]);
        float e0 = __ldg(&g_el2[s0]);
        float e1 = __ldg(&g_el2[s1]);
        float v00 = __ldg(&g_z2[s0 * 40 + lane]);
        float v10 = __ldg(&g_z2[s1 * 40 + lane]);
        float v01 = 0.f, v11 = 0.f;
        if (lane < 8) {
            v01 = __ldg(&g_z2[s0 * 40 + 32 + lane]);
            v11 = __ldg(&g_z2[s1 * 40 + 32 + lane]);
        }
        float x0 = __expf(lrelu(e0 + erd));
        float x1 = __expf(lrelu(e1 + erd));
        ds += x0 + x1;
        acc0 += x0 * v00 + x1 * v10;
        acc1 += x0 * v01 + x1 * v11;
    }
    if (j < end) {
        int s = __ldg(&g_csr[j]);
        float x = __expf(lrelu(__ldg(&g_el2[s]) + erd));
        ds += x;
        acc0 += x * __ldg(&g_z2[s * 40 + lane]);
        if (lane < 8) acc1 += x * __ldg(&g_z2[s * 40 + 32 + lane]);
    }
    float inv = (end > beg) ? 1.f / ds : 0.f;
    out[n * 40 + lane] = acc0 * inv + __ldg(b2 + lane);
    if (lane < 8) out[n * 40 + 32 + lane] = acc1 * inv + __ldg(b2 + 32 + lane);
}

// ---------------- launch ----------------
extern "C" void kernel_launch(void* const* d_in, const int* in_sizes, int n_in,
                              void* d_out, int out_size) {
    const float* feat = (const float*)d_in[0];
    const int*   src  = (const int*)d_in[1];
    const int*   dst  = (const int*)d_in[2];
    const float* W1   = (const float*)d_in[3];
    const float* al1  = (const float*)d_in[4];
    const float* ar1  = (const float*)d_in[5];
    const float* b1   = (const float*)d_in[6];
    const float* W2   = (const float*)d_in[7];
    const float* al2  = (const float*)d_in[8];
    const float* ar2  = (const float*)d_in[9];
    const float* b2   = (const float*)d_in[10];
    float* out = (float*)d_out;

    k_zero_deg<<<(NN + 255) / 256, 256>>>();
    k_hist<<<(NE + 255) / 256, 256>>>(dst);
    k_scanA<<<NB, 256>>>();
    k_scanB<<<1, 256>>>();
    k_scanC<<<NB, 256>>>();
    k_scatter<<<(NE + 255) / 256, 256>>>(src, dst);

    k_gemm1<<<(NN + 63) / 64, 256>>>(feat, W1, al1, ar1);
    k_agg1<<<(NN + 7) / 8, 256>>>(b1);

    k_gemm2<<<(NN + 63) / 64, 128>>>(W2, al2, ar2);
    k_agg2<<<(NN + 7) / 8, 256>>>(b2, out);
}

// round 3
// speedup vs baseline: 1.4274x; 1.0366x over previous
#include <cuda_runtime.h>
#include <cuda_fp16.h>
#include <math.h>

#define NN 50000
#define NE 800000
#define C1  256
#define H1  8
#define C2  40
#define NB  196   // (NN+255)/256

// ---------------- scratch ----------------
__device__ __half g_z1h[NN * C1];   // layer1 projected features, fp16 (gather source)
__device__ float g_h [NN * C1];     // elu(layer1 out), fp32
__device__ float g_el1[NN * H1];
__device__ float g_er1[NN * H1];
__device__ float g_z2[NN * C2];
__device__ float g_el2[NN];
__device__ float g_er2[NN];
__device__ int   g_deg[NN];
__device__ int   g_off[NN + 1];
__device__ int   g_cur[NN];
__device__ int   g_csr[NE];
__device__ int   g_bsum[NB];

// ---------------- CSR build ----------------
__global__ void k_zero_deg() {
    int i = blockIdx.x * blockDim.x + threadIdx.x;
    if (i < NN) g_deg[i] = 0;
}

__global__ void k_hist(const int* __restrict__ dst) {
    int i = blockIdx.x * blockDim.x + threadIdx.x;
    if (i < NE) atomicAdd(&g_deg[dst[i]], 1);
}

__global__ void k_scanA() {
    __shared__ int sd[256];
    int t = threadIdx.x;
    int i = blockIdx.x * 256 + t;
    sd[t] = (i < NN) ? g_deg[i] : 0;
    __syncthreads();
    for (int off = 128; off > 0; off >>= 1) {
        if (t < off) sd[t] += sd[t + off];
        __syncthreads();
    }
    if (t == 0) g_bsum[blockIdx.x] = sd[0];
}

__global__ void k_scanB() {
    __shared__ int sd[256];
    int t = threadIdx.x;
    int v = (t < NB) ? g_bsum[t] : 0;
    sd[t] = v;
    __syncthreads();
    for (int off = 1; off < 256; off <<= 1) {
        int u = 0;
        if (t >= off) u = sd[t - off];
        __syncthreads();
        if (t >= off) sd[t] += u;
        __syncthreads();
    }
    if (t < NB) g_bsum[t] = sd[t] - v;
    if (t == 255) g_off[NN] = sd[255];
}

__global__ void k_scanC() {
    __shared__ int sd[256];
    int t = threadIdx.x;
    int i = blockIdx.x * 256 + t;
    int v = (i < NN) ? g_deg[i] : 0;
    sd[t] = v;
    __syncthreads();
    for (int off = 1; off < 256; off <<= 1) {
        int u = 0;
        if (t >= off) u = sd[t - off];
        __syncthreads();
        if (t >= off) sd[t] += u;
        __syncthreads();
    }
    if (i < NN) {
        int ex = g_bsum[blockIdx.x] + sd[t] - v;
        g_off[i] = ex;
        g_cur[i] = ex;
    }
}

__global__ void k_scatter(const int* __restrict__ src, const int* __restrict__ dst) {
    int i = blockIdx.x * blockDim.x + threadIdx.x;
    if (i < NE) {
        int pos = atomicAdd(&g_cur[dst[i]], 1);
        g_csr[pos] = src[i];
    }
}

// ---------------- GEMM1 + fused el1/er1, fp16 z1 output ----------------
__global__ void k_gemm1(const float* __restrict__ A, const float* __restrict__ B,
                        const float* __restrict__ al1, const float* __restrict__ ar1) {
    __shared__ float As[8][64];
    __shared__ float Bs[8][256];
    const int K = 128;
    int by = blockIdx.x;
    int tid = threadIdx.x;
    int tx = tid & 31;
    int ty = tid >> 5;
    float acc[8][8];
#pragma unroll
    for (int i = 0; i < 8; i++)
#pragma unroll
        for (int j = 0; j < 8; j++) acc[i][j] = 0.f;

    int aRow = by * 64 + (tid >> 1);
    int aCol = (tid & 1) * 4;
    int bRow = tid >> 5;
    int bCol = (tid & 31) * 4;

    for (int k0 = 0; k0 < K; k0 += 8) {
        if (tid < 128) {
            float4 av = make_float4(0.f, 0.f, 0.f, 0.f);
            if (aRow < NN) av = *(const float4*)(A + aRow * K + k0 + aCol);
            As[aCol + 0][tid >> 1] = av.x;
            As[aCol + 1][tid >> 1] = av.y;
            As[aCol + 2][tid >> 1] = av.z;
            As[aCol + 3][tid >> 1] = av.w;
        }
        float4 bv0 = *(const float4*)(B + (k0 + bRow) * C1 + bCol);
        float4 bv1 = *(const float4*)(B + (k0 + bRow) * C1 + bCol + 128);
        *(float4*)&Bs[bRow][bCol] = bv0;
        *(float4*)&Bs[bRow][bCol + 128] = bv1;
        __syncthreads();
#pragma unroll
        for (int k = 0; k < 8; k++) {
            float4 a0 = *(float4*)&As[k][ty * 8];
            float4 a1 = *(float4*)&As[k][ty * 8 + 4];
            float4 b0 = *(float4*)&Bs[k][tx * 8];
            float4 b1 = *(float4*)&Bs[k][tx * 8 + 4];
            float af[8] = {a0.x, a0.y, a0.z, a0.w, a1.x, a1.y, a1.z, a1.w};
            float bf[8] = {b0.x, b0.y, b0.z, b0.w, b1.x, b1.y, b1.z, b1.w};
#pragma unroll
            for (int i = 0; i < 8; i++)
#pragma unroll
                for (int j = 0; j < 8; j++) acc[i][j] += af[i] * bf[j];
        }
        __syncthreads();
    }

    float alv[8], arv[8];
#pragma unroll
    for (int j = 0; j < 8; j++) {
        alv[j] = __ldg(al1 + tx * 8 + j);
        arv[j] = __ldg(ar1 + tx * 8 + j);
    }
    int h = tx >> 2;
#pragma unroll
    for (int i = 0; i < 8; i++) {
        int row = by * 64 + ty * 8 + i;
        float pel = 0.f, per = 0.f;
#pragma unroll
        for (int j = 0; j < 8; j++) {
            pel += acc[i][j] * alv[j];
            per += acc[i][j] * arv[j];
        }
        pel += __shfl_xor_sync(0xffffffffu, pel, 1);
        per += __shfl_xor_sync(0xffffffffu, per, 1);
        pel += __shfl_xor_sync(0xffffffffu, pel, 2);
        per += __shfl_xor_sync(0xffffffffu, per, 2);
        if (row < NN) {
            __half2 p0 = __floats2half2_rn(acc[i][0], acc[i][1]);
            __half2 p1 = __floats2half2_rn(acc[i][2], acc[i][3]);
            __half2 p2 = __floats2half2_rn(acc[i][4], acc[i][5]);
            __half2 p3 = __floats2half2_rn(acc[i][6], acc[i][7]);
            uint4 pk;
            pk.x = *(unsigned*)&p0; pk.y = *(unsigned*)&p1;
            pk.z = *(unsigned*)&p2; pk.w = *(unsigned*)&p3;
            *(uint4*)(g_z1h + row * 256 + tx * 8) = pk;
            if ((tx & 3) == 0) {
                g_el1[row * 8 + h] = pel;
                g_er1[row * 8 + h] = per;
            }
        }
    }
}

__device__ __forceinline__ float lrelu(float x) { return x > 0.f ? x : 0.2f * x; }
__device__ __forceinline__ float elu(float x)  { return x > 0.f ? x : __expf(x) - 1.f; }

// ---------------- layer1 aggregation: 2 warps/node, fp16 gather, unroll-4 ----------------
__global__ void k_agg1(const float* __restrict__ b1) {
    int wslot = threadIdx.x >> 5;            // 0..7
    int n = blockIdx.x * 4 + (wslot >> 1);   // 4 nodes/block
    if (n >= NN) return;
    int w = wslot & 1;                       // which 128-channel half
    int lane = threadIdx.x & 31;
    int c0 = w * 128 + lane * 4;             // my 4 channels
    int h = c0 >> 5;                         // my head
    int beg = g_off[n], end = g_off[n + 1];
    float erd = g_er1[n * 8 + h];
    float4 acc = make_float4(0.f, 0.f, 0.f, 0.f);
    float ds = 0.f;
    const __half* zb = g_z1h + c0;

    int j = beg;
    for (; j + 4 <= end; j += 4) {
        int s0 = __ldg(&g_csr[j + 0]);
        int s1 = __ldg(&g_csr[j + 1]);
        int s2 = __ldg(&g_csr[j + 2]);
        int s3 = __ldg(&g_csr[j + 3]);
        float e0 = __ldg(&g_el1[s0 * 8 + h]);
        float e1 = __ldg(&g_el1[s1 * 8 + h]);
        float e2 = __ldg(&g_el1[s2 * 8 + h]);
        float e3 = __ldg(&g_el1[s3 * 8 + h]);
        uint2 v0 = __ldg((const uint2*)(zb + s0 * 256));
        uint2 v1 = __ldg((const uint2*)(zb + s1 * 256));
        uint2 v2 = __ldg((const uint2*)(zb + s2 * 256));
        uint2 v3 = __ldg((const uint2*)(zb + s3 * 256));
        float x0 = __expf(lrelu(e0 + erd));
        float x1 = __expf(lrelu(e1 + erd));
        float x2 = __expf(lrelu(e2 + erd));
        float x3 = __expf(lrelu(e3 + erd));
        ds += (x0 + x1) + (x2 + x3);
        float2 a0 = __half22float2(*(__half2*)&v0.x);
        float2 b0 = __half22float2(*(__half2*)&v0.y);
        float2 a1 = __half22float2(*(__half2*)&v1.x);
        float2 b1v = __half22float2(*(__half2*)&v1.y);
        float2 a2 = __half22float2(*(__half2*)&v2.x);
        float2 b2v = __half22float2(*(__half2*)&v2.y);
        float2 a3 = __half22float2(*(__half2*)&v3.x);
        float2 b3 = __half22float2(*(__half2*)&v3.y);
        acc.x += x0 * a0.x + x1 * a1.x + x2 * a2.x + x3 * a3.x;
        acc.y += x0 * a0.y + x1 * a1.y + x2 * a2.y + x3 * a3.y;
        acc.z += x0 * b0.x + x1 * b1v.x + x2 * b2v.x + x3 * b3.x;
        acc.w += x0 * b0.y + x1 * b1v.y + x2 * b2v.y + x3 * b3.y;
    }
    for (; j < end; j++) {
        int s = __ldg(&g_csr[j]);
        float x = __expf(lrelu(__ldg(&g_el1[s * 8 + h]) + erd));
        uint2 v = __ldg((const uint2*)(zb + s * 256));
        ds += x;
        float2 a = __half22float2(*(__half2*)&v.x);
        float2 b = __half22float2(*(__half2*)&v.y);
        acc.x += x * a.x; acc.y += x * a.y;
        acc.z += x * b.x; acc.w += x * b.y;
    }
    float inv = (end > beg) ? 1.f / ds : 0.f;
    float4 bb = *(const float4*)(b1 + c0);
    float4 o;
    o.x = elu(acc.x * inv + bb.x);
    o.y = elu(acc.y * inv + bb.y);
    o.z = elu(acc.z * inv + bb.z);
    o.w = elu(acc.w * inv + bb.w);
    *(float4*)(g_h + n * 256 + c0) = o;
}

// ---------------- GEMM2 + fused el2/er2 ----------------
__global__ void k_gemm2(const float* __restrict__ W2,
                        const float* __restrict__ al2, const float* __restrict__ ar2) {
    __shared__ float Bs[256 * 40];
    __shared__ float As[16][64];
    int by = blockIdx.x;
    int tid = threadIdx.x;
    int tx = tid & 7;
    int ty = tid >> 3;
    {
        const float4* wp = (const float4*)W2;
        float4* bp = (float4*)Bs;
        for (int i = tid; i < 2560; i += 128) bp[i] = wp[i];
    }
    float acc[4][5];
#pragma unroll
    for (int i = 0; i < 4; i++)
#pragma unroll
        for (int j = 0; j < 5; j++) acc[i][j] = 0.f;

    for (int k0 = 0; k0 < 256; k0 += 16) {
        __syncthreads();
        for (int q = 0; q < 2; q++) {
            int li = tid + q * 128;
            int row = li >> 2;
            int ck  = (li & 3) * 4;
            int grow = by * 64 + row;
            float4 v = make_float4(0.f, 0.f, 0.f, 0.f);
            if (grow < NN) v = *(const float4*)(g_h + grow * 256 + k0 + ck);
            As[ck + 0][row] = v.x;
            As[ck + 1][row] = v.y;
            As[ck + 2][row] = v.z;
            As[ck + 3][row] = v.w;
        }
        __syncthreads();
#pragma unroll
        for (int kk = 0; kk < 16; kk++) {
            float af[4], bf[5];
#pragma unroll
            for (int i = 0; i < 4; i++) af[i] = As[kk][ty * 4 + i];
#pragma unroll
            for (int j = 0; j < 5; j++) bf[j] = Bs[(k0 + kk) * 40 + tx * 5 + j];
#pragma unroll
            for (int i = 0; i < 4; i++)
#pragma unroll
                for (int j = 0; j < 5; j++) acc[i][j] += af[i] * bf[j];
        }
    }
    float alv[5], arv[5];
#pragma unroll
    for (int j = 0; j < 5; j++) {
        alv[j] = __ldg(al2 + tx * 5 + j);
        arv[j] = __ldg(ar2 + tx * 5 + j);
    }
#pragma unroll
    for (int i = 0; i < 4; i++) {
        int row = by * 64 + ty * 4 + i;
        float pel = 0.f, per = 0.f;
#pragma unroll
        for (int j = 0; j < 5; j++) {
            pel += acc[i][j] * alv[j];
            per += acc[i][j] * arv[j];
        }
        pel += __shfl_xor_sync(0xffffffffu, pel, 1);
        per += __shfl_xor_sync(0xffffffffu, per, 1);
        pel += __shfl_xor_sync(0xffffffffu, pel, 2);
        per += __shfl_xor_sync(0xffffffffu, per, 2);
        pel += __shfl_xor_sync(0xffffffffu, pel, 4);
        per += __shfl_xor_sync(0xffffffffu, per, 4);
        if (row < NN) {
#pragma unroll
            for (int j = 0; j < 5; j++) g_z2[row * 40 + tx * 5 + j] = acc[i][j];
            if (tx == 0) {
                g_el2[row] = pel;
                g_er2[row] = per;
            }
        }
    }
}

// ---------------- layer2 aggregation (warp/node, unroll-4) ----------------
__global__ void k_agg2(const float* __restrict__ b2, float* __restrict__ out) {
    int n = blockIdx.x * 8 + (threadIdx.x >> 5);
    if (n >= NN) return;
    int lane = threadIdx.x & 31;
    int beg = g_off[n], end = g_off[n + 1];
    float erd = g_er2[n];
    float acc0 = 0.f, acc1 = 0.f, ds = 0.f;
    int j = beg;
    for (; j + 4 <= end; j += 4) {
        int s0 = __ldg(&g_csr[j + 0]);
        int s1 = __ldg(&g_csr[j + 1]);
        int s2 = __ldg(&g_csr[j + 2]);
        int s3 = __ldg(&g_csr[j + 3]);
        float e0 = __ldg(&g_el2[s0]);
        float e1 = __ldg(&g_el2[s1]);
        float e2 = __ldg(&g_el2[s2]);
        float e3 = __ldg(&g_el2[s3]);
        float v0 = __ldg(&g_z2[s0 * 40 + lane]);
        float v1 = __ldg(&g_z2[s1 * 40 + lane]);
        float v2 = __ldg(&g_z2[s2 * 40 + lane]);
        float v3 = __ldg(&g_z2[s3 * 40 + lane]);
        float u0 = 0.f, u1 = 0.f, u2 = 0.f, u3 = 0.f;
        if (lane < 8) {
            u0 = __ldg(&g_z2[s0 * 40 + 32 + lane]);
            u1 = __ldg(&g_z2[s1 * 40 + 32 + lane]);
            u2 = __ldg(&g_z2[s2 * 40 + 32 + lane]);
            u3 = __ldg(&g_z2[s3 * 40 + 32 + lane]);
        }
        float x0 = __expf(lrelu(e0 + erd));
        float x1 = __expf(lrelu(e1 + erd));
        float x2 = __expf(lrelu(e2 + erd));
        float x3 = __expf(lrelu(e3 + erd));
        ds += (x0 + x1) + (x2 + x3);
        acc0 += x0 * v0 + x1 * v1 + x2 * v2 + x3 * v3;
        acc1 += x0 * u0 + x1 * u1 + x2 * u2 + x3 * u3;
    }
    for (; j < end; j++) {
        int s = __ldg(&g_csr[j]);
        float x = __expf(lrelu(__ldg(&g_el2[s]) + erd));
        ds += x;
        acc0 += x * __ldg(&g_z2[s * 40 + lane]);
        if (lane < 8) acc1 += x * __ldg(&g_z2[s * 40 + 32 + lane]);
    }
    float inv = (end > beg) ? 1.f / ds : 0.f;
    out[n * 40 + lane] = acc0 * inv + __ldg(b2 + lane);
    if (lane < 8) out[n * 40 + 32 + lane] = acc1 * inv + __ldg(b2 + 32 + lane);
}

// ---------------- launch ----------------
extern "C" void kernel_launch(void* const* d_in, const int* in_sizes, int n_in,
                              void* d_out, int out_size) {
    const float* feat = (const float*)d_in[0];
    const int*   src  = (const int*)d_in[1];
    const int*   dst  = (const int*)d_in[2];
    const float* W1   = (const float*)d_in[3];
    const float* al1  = (const float*)d_in[4];
    const float* ar1  = (const float*)d_in[5];
    const float* b1   = (const float*)d_in[6];
    const float* W2   = (const float*)d_in[7];
    const float* al2  = (const float*)d_in[8];
    const float* ar2  = (const float*)d_in[9];
    const float* b2   = (const float*)d_in[10];
    float* out = (float*)d_out;

    k_zero_deg<<<(NN + 255) / 256, 256>>>();
    k_hist<<<(NE + 255) / 256, 256>>>(dst);
    k_scanA<<<NB, 256>>>();
    k_scanB<<<1, 256>>>();
    k_scanC<<<NB, 256>>>();
    k_scatter<<<(NE + 255) / 256, 256>>>(src, dst);

    k_gemm1<<<(NN + 63) / 64, 256>>>(feat, W1, al1, ar1);
    k_agg1<<<(NN + 3) / 4, 256>>>(b1);

    k_gemm2<<<(NN + 63) / 64, 128>>>(W2, al2, ar2);
    k_agg2<<<(NN + 7) / 8, 256>>>(b2, out);
}

// round 7
// speedup vs baseline: 2.2402x; 1.5695x over previous
#include <cuda_runtime.h>
#include <cuda_fp16.h>
#include <math.h>

#define NN 50000
#define NE 800000
#define C1  256
#define H1  8
#define C2  40
#define NB  196

// ---------------- scratch ----------------
__device__ __half g_z1h[NN * C1];   // layer1 projected features, fp16
__device__ __half g_hh [NN * C1];   // elu(layer1 out), fp16
__device__ float g_el1[NN * H1];
__device__ float g_er1[NN * H1];
__device__ float g_z2[NN * C2];
__device__ float g_el2[NN];
__device__ float g_er2[NN];
__device__ int   g_deg[NN];
__device__ int   g_off[NN + 1];
__device__ int   g_cur[NN];
__device__ int   g_csr[NE];
__device__ int   g_bsum[NB];

// ---------------- CSR build ----------------
__global__ void k_zero_deg() {
    int i = blockIdx.x * blockDim.x + threadIdx.x;
    if (i < NN) g_deg[i] = 0;
}

__global__ void k_hist(const int* __restrict__ dst) {
    int i = blockIdx.x * blockDim.x + threadIdx.x;
    if (i < NE) atomicAdd(&g_deg[dst[i]], 1);
}

__global__ void k_scanA() {
    __shared__ int sd[256];
    int t = threadIdx.x;
    int i = blockIdx.x * 256 + t;
    sd[t] = (i < NN) ? g_deg[i] : 0;
    __syncthreads();
    for (int off = 128; off > 0; off >>= 1) {
        if (t < off) sd[t] += sd[t + off];
        __syncthreads();
    }
    if (t == 0) g_bsum[blockIdx.x] = sd[0];
}

__global__ void k_scanB() {
    __shared__ int sd[256];
    int t = threadIdx.x;
    int v = (t < NB) ? g_bsum[t] : 0;
    sd[t] = v;
    __syncthreads();
    for (int off = 1; off < 256; off <<= 1) {
        int u = 0;
        if (t >= off) u = sd[t - off];
        __syncthreads();
        if (t >= off) sd[t] += u;
        __syncthreads();
    }
    if (t < NB) g_bsum[t] = sd[t] - v;
    if (t == 255) g_off[NN] = sd[255];
}

__global__ void k_scanC() {
    __shared__ int sd[256];
    int t = threadIdx.x;
    int i = blockIdx.x * 256 + t;
    int v = (i < NN) ? g_deg[i] : 0;
    sd[t] = v;
    __syncthreads();
    for (int off = 1; off < 256; off <<= 1) {
        int u = 0;
        if (t >= off) u = sd[t - off];
        __syncthreads();
        if (t >= off) sd[t] += u;
        __syncthreads();
    }
    if (i < NN) {
        int ex = g_bsum[blockIdx.x] + sd[t] - v;
        g_off[i] = ex;
        g_cur[i] = ex;
    }
}

__global__ void k_scatter(const int* __restrict__ src, const int* __restrict__ dst) {
    int i = blockIdx.x * blockDim.x + threadIdx.x;
    if (i < NE) {
        int pos = atomicAdd(&g_cur[dst[i]], 1);
        g_csr[pos] = src[i];
    }
}

__device__ __forceinline__ float lrelu(float x) { return x > 0.f ? x : 0.2f * x; }
__device__ __forceinline__ float elu(float x)  { return x > 0.f ? x : __expf(x) - 1.f; }

__device__ __forceinline__ void mma16816(float* d, const unsigned* a, const unsigned* b) {
    asm volatile(
        "mma.sync.aligned.m16n8k16.row.col.f32.f16.f16.f32 "
        "{%0,%1,%2,%3}, {%4,%5,%6,%7}, {%8,%9}, {%0,%1,%2,%3};"
        : "+f"(d[0]), "+f"(d[1]), "+f"(d[2]), "+f"(d[3])
        : "r"(a[0]), "r"(a[1]), "r"(a[2]), "r"(a[3]), "r"(b[0]), "r"(b[1]));
}

// ---------------- GEMM1 (tensor core) + fused el1/er1 ----------------
// z1h[N,256] = feat[N,128] @ W1[128,256]; BM=64, BN=256(full), BK=64, 256 thr
#define AS1 72   // A row stride (halfs)
#define BS1 76   // B row stride (halfs)
__global__ __launch_bounds__(256) void k_gemm1(
        const float* __restrict__ A, const float* __restrict__ B,
        const float* __restrict__ al1, const float* __restrict__ ar1) {
    __shared__ __align__(16) __half As[64 * AS1];
    __shared__ __align__(16) __half Bs[256 * BS1];
    int by = blockIdx.x;
    int tid = threadIdx.x;
    int wid = tid >> 5, lane = tid & 31;
    int g = lane >> 2, t4 = lane & 3;
    int warp_m = wid >> 2, warp_n = wid & 3;
    int rowbase = warp_m * 32;
    int colbase = warp_n * 64;

    float d[2][8][4];
#pragma unroll
    for (int mt = 0; mt < 2; mt++)
#pragma unroll
        for (int nt = 0; nt < 8; nt++)
#pragma unroll
            for (int q = 0; q < 4; q++) d[mt][nt][q] = 0.f;

    for (int k0 = 0; k0 < 128; k0 += 64) {
        // load A chunk: 64 rows x 64 cols fp32 -> fp16
#pragma unroll
        for (int q = 0; q < 4; q++) {
            int li = tid + q * 256;          // 0..1023
            int row = li >> 4;
            int c4 = (li & 15) * 4;
            int grow = by * 64 + row;
            float4 av = make_float4(0.f, 0.f, 0.f, 0.f);
            if (grow < NN) av = *(const float4*)(A + grow * 128 + k0 + c4);
            __half2 h0 = __floats2half2_rn(av.x, av.y);
            __half2 h1 = __floats2half2_rn(av.z, av.w);
            *(__half2*)&As[row * AS1 + c4] = h0;
            *(__half2*)&As[row * AS1 + c4 + 2] = h1;
        }
        // load B chunk transposed: W1[k][n] -> Bs[n][k]
#pragma unroll
        for (int q = 0; q < 16; q++) {
            int li = tid + q * 256;          // 0..4095
            int k = li >> 6;
            int n = (li & 63) * 4;
            float4 bv = *(const float4*)(B + (k0 + k) * 256 + n);
            Bs[(n + 0) * BS1 + k] = __float2half_rn(bv.x);
            Bs[(n + 1) * BS1 + k] = __float2half_rn(bv.y);
            Bs[(n + 2) * BS1 + k] = __float2half_rn(bv.z);
            Bs[(n + 3) * BS1 + k] = __float2half_rn(bv.w);
        }
        __syncthreads();
#pragma unroll
        for (int ks = 0; ks < 4; ks++) {
            unsigned a[2][4];
#pragma unroll
            for (int mt = 0; mt < 2; mt++) {
                const __half* ap = &As[(rowbase + mt * 16 + g) * AS1 + ks * 16 + t4 * 2];
                const __half* ap8 = ap + 8 * AS1;
                a[mt][0] = *(const unsigned*)ap;
                a[mt][1] = *(const unsigned*)ap8;
                a[mt][2] = *(const unsigned*)(ap + 8);
                a[mt][3] = *(const unsigned*)(ap8 + 8);
            }
            unsigned b[8][2];
#pragma unroll
            for (int nt = 0; nt < 8; nt++) {
                const __half* bp = &Bs[(colbase + nt * 8 + g) * BS1 + ks * 16 + t4 * 2];
                b[nt][0] = *(const unsigned*)bp;
                b[nt][1] = *(const unsigned*)(bp + 8);
            }
#pragma unroll
            for (int mt = 0; mt < 2; mt++)
#pragma unroll
                for (int nt = 0; nt < 8; nt++) mma16816(d[mt][nt], a[mt], b[nt]);
        }
        __syncthreads();
    }

    // epilogue: fp16 z1 store + fused per-head attention dots
    float alv[8][2], arv[8][2];
#pragma unroll
    for (int nt = 0; nt < 8; nt++) {
        int c = colbase + nt * 8 + t4 * 2;
        alv[nt][0] = __ldg(al1 + c);     alv[nt][1] = __ldg(al1 + c + 1);
        arv[nt][0] = __ldg(ar1 + c);     arv[nt][1] = __ldg(ar1 + c + 1);
    }
#pragma unroll
    for (int mt = 0; mt < 2; mt++) {
#pragma unroll
        for (int hf = 0; hf < 2; hf++) {
            int row = by * 64 + rowbase + mt * 16 + g + hf * 8;
            float p0l = 0.f, p0r = 0.f, p1l = 0.f, p1r = 0.f;
#pragma unroll
            for (int nt = 0; nt < 8; nt++) {
                float v0 = d[mt][nt][hf * 2 + 0];
                float v1 = d[mt][nt][hf * 2 + 1];
                float pl = v0 * alv[nt][0] + v1 * alv[nt][1];
                float pr = v0 * arv[nt][0] + v1 * arv[nt][1];
                if (nt < 4) { p0l += pl; p0r += pr; }
                else        { p1l += pl; p1r += pr; }
            }
            p0l += __shfl_xor_sync(0xffffffffu, p0l, 1);
            p0r += __shfl_xor_sync(0xffffffffu, p0r, 1);
            p1l += __shfl_xor_sync(0xffffffffu, p1l, 1);
            p1r += __shfl_xor_sync(0xffffffffu, p1r, 1);
            p0l += __shfl_xor_sync(0xffffffffu, p0l, 2);
            p0r += __shfl_xor_sync(0xffffffffu, p0r, 2);
            p1l += __shfl_xor_sync(0xffffffffu, p1l, 2);
            p1r += __shfl_xor_sync(0xffffffffu, p1r, 2);
            if (row < NN) {
#pragma unroll
                for (int nt = 0; nt < 8; nt++) {
                    __half2 hv = __floats2half2_rn(d[mt][nt][hf * 2], d[mt][nt][hf * 2 + 1]);
                    *(__half2*)(g_z1h + row * 256 + colbase + nt * 8 + t4 * 2) = hv;
                }
                if (t4 == 0) {
                    int h = warp_n * 2;
                    g_el1[row * 8 + h]     = p0l;
                    g_er1[row * 8 + h]     = p0r;
                    g_el1[row * 8 + h + 1] = p1l;
                    g_er1[row * 8 + h + 1] = p1r;
                }
            }
        }
    }
}

// ---------------- layer1 aggregation: 1 warp/node, uint4 fp16 gather ----------------
__global__ void k_agg1(const float* __restrict__ b1) {
    int n = blockIdx.x * 8 + (threadIdx.x >> 5);
    if (n >= NN) return;
    int lane = threadIdx.x & 31;
    int c0 = lane * 8;                 // my 8 channels
    int h = lane >> 2;                 // my head
    int beg = g_off[n], end = g_off[n + 1];
    float erd = g_er1[n * 8 + h];
    float acc[8];
#pragma unroll
    for (int q = 0; q < 8; q++) acc[q] = 0.f;
    float ds = 0.f;
    const __half* zb = g_z1h + c0;

    int j = beg;
    for (; j + 4 <= end; j += 4) {
        int s0 = __ldg(&g_csr[j + 0]);
        int s1 = __ldg(&g_csr[j + 1]);
        int s2 = __ldg(&g_csr[j + 2]);
        int s3 = __ldg(&g_csr[j + 3]);
        float e0 = __ldg(&g_el1[s0 * 8 + h]);
        float e1 = __ldg(&g_el1[s1 * 8 + h]);
        float e2 = __ldg(&g_el1[s2 * 8 + h]);
        float e3 = __ldg(&g_el1[s3 * 8 + h]);
        uint4 v0 = __ldg((const uint4*)(zb + s0 * 256));
        uint4 v1 = __ldg((const uint4*)(zb + s1 * 256));
        uint4 v2 = __ldg((const uint4*)(zb + s2 * 256));
        uint4 v3 = __ldg((const uint4*)(zb + s3 * 256));
        float x0 = __expf(lrelu(e0 + erd));
        float x1 = __expf(lrelu(e1 + erd));
        float x2 = __expf(lrelu(e2 + erd));
        float x3 = __expf(lrelu(e3 + erd));
        ds += (x0 + x1) + (x2 + x3);
        const unsigned* p0 = &v0.x; const unsigned* p1 = &v1.x;
        const unsigned* p2 = &v2.x; const unsigned* p3 = &v3.x;
#pragma unroll
        for (int q = 0; q < 4; q++) {
            float2 f0 = __half22float2(*(const __half2*)&p0[q]);
            float2 f1 = __half22float2(*(const __half2*)&p1[q]);
            float2 f2 = __half22float2(*(const __half2*)&p2[q]);
            float2 f3 = __half22float2(*(const __half2*)&p3[q]);
            acc[q * 2 + 0] += x0 * f0.x + x1 * f1.x + x2 * f2.x + x3 * f3.x;
            acc[q * 2 + 1] += x0 * f0.y + x1 * f1.y + x2 * f2.y + x3 * f3.y;
        }
    }
    for (; j < end; j++) {
        int s = __ldg(&g_csr[j]);
        float x = __expf(lrelu(__ldg(&g_el1[s * 8 + h]) + erd));
        uint4 v = __ldg((const uint4*)(zb + s * 256));
        ds += x;
        const unsigned* p = &v.x;
#pragma unroll
        for (int q = 0; q < 4; q++) {
            float2 f = __half22float2(*(const __half2*)&p[q]);
            acc[q * 2 + 0] += x * f.x;
            acc[q * 2 + 1] += x * f.y;
        }
    }
    float inv = (end > beg) ? 1.f / ds : 0.f;
    float4 bb0 = *(const float4*)(b1 + c0);
    float4 bb1 = *(const float4*)(b1 + c0 + 4);
    float o[8];
    o[0] = elu(acc[0] * inv + bb0.x); o[1] = elu(acc[1] * inv + bb0.y);
    o[2] = elu(acc[2] * inv + bb0.z); o[3] = elu(acc[3] * inv + bb0.w);
    o[4] = elu(acc[4] * inv + bb1.x); o[5] = elu(acc[5] * inv + bb1.y);
    o[6] = elu(acc[6] * inv + bb1.z); o[7] = elu(acc[7] * inv + bb1.w);
    uint4 pk;
    __half2 q0 = __floats2half2_rn(o[0], o[1]);
    __half2 q1 = __floats2half2_rn(o[2], o[3]);
    __half2 q2 = __floats2half2_rn(o[4], o[5]);
    __half2 q3 = __floats2half2_rn(o[6], o[7]);
    pk.x = *(unsigned*)&q0; pk.y = *(unsigned*)&q1;
    pk.z = *(unsigned*)&q2; pk.w = *(unsigned*)&q3;
    *(uint4*)(g_hh + n * 256 + c0) = pk;
}

// ---------------- GEMM2 (tensor core) + fused el2/er2 ----------------
// z2[N,40] = h[N,256] @ W2[256,40]; BM=128, BK=64, 256 thr, warp = 16 rows x 40 cols
#define AS2 72
#define BS2 76
__global__ __launch_bounds__(256) void k_gemm2(
        const float* __restrict__ W2,
        const float* __restrict__ al2, const float* __restrict__ ar2) {
    __shared__ __align__(16) __half As[128 * AS2];
    __shared__ __align__(16) __half Bs[40 * BS2];
    int by = blockIdx.x;
    int tid = threadIdx.x;
    int wid = tid >> 5, lane = tid & 31;
    int g = lane >> 2, t4 = lane & 3;

    float d[5][4];
#pragma unroll
    for (int nt = 0; nt < 5; nt++)
#pragma unroll
        for (int q = 0; q < 4; q++) d[nt][q] = 0.f;

    for (int k0 = 0; k0 < 256; k0 += 64) {
        // A: g_hh rows (already fp16) - 128 rows x 64 halfs = 1024 uint4
#pragma unroll
        for (int q = 0; q < 4; q++) {
            int li = tid + q * 256;            // 0..1023
            int row = li >> 3;                 // 0..127
            int c8 = (li & 7) * 8;             // 0..56
            int grow = by * 128 + row;
            uint4 v = make_uint4(0, 0, 0, 0);
            if (grow < NN) v = *(const uint4*)(g_hh + grow * 256 + k0 + c8);
            *(uint4*)&As[row * AS2 + c8] = v;
        }
        // B: W2[k][40] fp32 -> Bs[n][k] fp16
        for (int li = tid; li < 640; li += 256) {
            int k = li / 10;
            int n = (li % 10) * 4;
            float4 bv = *(const float4*)(W2 + (k0 + k) * 40 + n);
            Bs[(n + 0) * BS2 + k] = __float2half_rn(bv.x);
            Bs[(n + 1) * BS2 + k] = __float2half_rn(bv.y);
            Bs[(n + 2) * BS2 + k] = __float2half_rn(bv.z);
            Bs[(n + 3) * BS2 + k] = __float2half_rn(bv.w);
        }
        __syncthreads();
#pragma unroll
        for (int ks = 0; ks < 4; ks++) {
            unsigned a[4];
            const __half* ap = &As[(wid * 16 + g) * AS2 + ks * 16 + t4 * 2];
            const __half* ap8 = ap + 8 * AS2;
            a[0] = *(const unsigned*)ap;
            a[1] = *(const unsigned*)ap8;
            a[2] = *(const unsigned*)(ap + 8);
            a[3] = *(const unsigned*)(ap8 + 8);
            unsigned b[5][2];
#pragma unroll
            for (int nt = 0; nt < 5; nt++) {
                const __half* bp = &Bs[(nt * 8 + g) * BS2 + ks * 16 + t4 * 2];
                b[nt][0] = *(const unsigned*)bp;
                b[nt][1] = *(const unsigned*)(bp + 8);
            }
#pragma unroll
            for (int nt = 0; nt < 5; nt++) mma16816(d[nt], a, b[nt]);
        }
        __syncthreads();
    }

    float alv[5][2], arv[5][2];
#pragma unroll
    for (int nt = 0; nt < 5; nt++) {
        int c = nt * 8 + t4 * 2;
        alv[nt][0] = __ldg(al2 + c);     alv[nt][1] = __ldg(al2 + c + 1);
        arv[nt][0] = __ldg(ar2 + c);     arv[nt][1] = __ldg(ar2 + c + 1);
    }
#pragma unroll
    for (int hf = 0; hf < 2; hf++) {
        int row = by * 128 + wid * 16 + g + hf * 8;
        float pl = 0.f, pr = 0.f;
#pragma unroll
        for (int nt = 0; nt < 5; nt++) {
            float v0 = d[nt][hf * 2 + 0];
            float v1 = d[nt][hf * 2 + 1];
            pl += v0 * alv[nt][0] + v1 * alv[nt][1];
            pr += v0 * arv[nt][0] + v1 * arv[nt][1];
        }
        pl += __shfl_xor_sync(0xffffffffu, pl, 1);
        pr += __shfl_xor_sync(0xffffffffu, pr, 1);
        pl += __shfl_xor_sync(0xffffffffu, pl, 2);
        pr += __shfl_xor_sync(0xffffffffu, pr, 2);
        if (row < NN) {
#pragma unroll
            for (int nt = 0; nt < 5; nt++) {
                float2 fv = make_float2(d[nt][hf * 2], d[nt][hf * 2 + 1]);
                *(float2*)(g_z2 + row * 40 + nt * 8 + t4 * 2) = fv;
            }
            if (t4 == 0) {
                g_el2[row] = pl;
                g_er2[row] = pr;
            }
        }
    }
}

// ---------------- layer2 aggregation (warp/node, unroll-4) ----------------
__global__ void k_agg2(const float* __restrict__ b2, float* __restrict__ out) {
    int n = blockIdx.x * 8 + (threadIdx.x >> 5);
    if (n >= NN) return;
    int lane = threadIdx.x & 31;
    int beg = g_off[n], end = g_off[n + 1];
    float erd = g_er2[n];
    float acc0 = 0.f, acc1 = 0.f, ds = 0.f;
    int j = beg;
    for (; j + 4 <= end; j += 4) {
        int s0 = __ldg(&g_csr[j + 0]);
        int s1 = __ldg(&g_csr[j + 1]);
        int s2 = __ldg(&g_csr[j + 2]);
        int s3 = __ldg(&g_csr[j + 3]);
        float e0 = __ldg(&g_el2[s0]);
        float e1 = __ldg(&g_el2[s1]);
        float e2 = __ldg(&g_el2[s2]);
        float e3 = __ldg(&g_el2[s3]);
        float v0 = __ldg(&g_z2[s0 * 40 + lane]);
        float v1 = __ldg(&g_z2[s1 * 40 + lane]);
        float v2 = __ldg(&g_z2[s2 * 40 + lane]);
        float v3 = __ldg(&g_z2[s3 * 40 + lane]);
        float u0 = 0.f, u1 = 0.f, u2 = 0.f, u3 = 0.f;
        if (lane < 8) {
            u0 = __ldg(&g_z2[s0 * 40 + 32 + lane]);
            u1 = __ldg(&g_z2[s1 * 40 + 32 + lane]);
            u2 = __ldg(&g_z2[s2 * 40 + 32 + lane]);
            u3 = __ldg(&g_z2[s3 * 40 + 32 + lane]);
        }
        float x0 = __expf(lrelu(e0 + erd));
        float x1 = __expf(lrelu(e1 + erd));
        float x2 = __expf(lrelu(e2 + erd));
        float x3 = __expf(lrelu(e3 + erd));
        ds += (x0 + x1) + (x2 + x3);
        acc0 += x0 * v0 + x1 * v1 + x2 * v2 + x3 * v3;
        acc1 += x0 * u0 + x1 * u1 + x2 * u2 + x3 * u3;
    }
    for (; j < end; j++) {
        int s = __ldg(&g_csr[j]);
        float x = __expf(lrelu(__ldg(&g_el2[s]) + erd));
        ds += x;
        acc0 += x * __ldg(&g_z2[s * 40 + lane]);
        if (lane < 8) acc1 += x * __ldg(&g_z2[s * 40 + 32 + lane]);
    }
    float inv = (end > beg) ? 1.f / ds : 0.f;
    out[n * 40 + lane] = acc0 * inv + __ldg(b2 + lane);
    if (lane < 8) out[n * 40 + 32 + lane] = acc1 * inv + __ldg(b2 + 32 + lane);
}

// ---------------- launch ----------------
extern "C" void kernel_launch(void* const* d_in, const int* in_sizes, int n_in,
                              void* d_out, int out_size) {
    const float* feat = (const float*)d_in[0];
    const int*   src  = (const int*)d_in[1];
    const int*   dst  = (const int*)d_in[2];
    const float* W1   = (const float*)d_in[3];
    const float* al1  = (const float*)d_in[4];
    const float* ar1  = (const float*)d_in[5];
    const float* b1   = (const float*)d_in[6];
    const float* W2   = (const float*)d_in[7];
    const float* al2  = (const float*)d_in[8];
    const float* ar2  = (const float*)d_in[9];
    const float* b2   = (const float*)d_in[10];
    float* out = (float*)d_out;

    k_zero_deg<<<(NN + 255) / 256, 256>>>();
    k_hist<<<(NE + 255) / 256, 256>>>(dst);
    k_scanA<<<NB, 256>>>();
    k_scanB<<<1, 256>>>();
    k_scanC<<<NB, 256>>>();
    k_scatter<<<(NE + 255) / 256, 256>>>(src, dst);

    k_gemm1<<<(NN + 63) / 64, 256>>>(feat, W1, al1, ar1);
    k_agg1<<<(NN + 7) / 8, 256>>>(b1);

    k_gemm2<<<(NN + 127) / 128, 256>>>(W2, al2, ar2);
    k_agg2<<<(NN + 7) / 8, 256>>>(b2, out);
}

// round 9
// speedup vs baseline: 2.3505x; 1.0492x over previous
#include <cuda_runtime.h>
#include <cuda_fp16.h>
#include <math.h>

#define NN 50000
#define NE 800000
#define C1  256
#define H1  8
#define C2  40
#define NB  196

// ---------------- scratch ----------------
__device__ __half g_z1h[NN * C1];   // layer1 projected features, fp16
__device__ __half g_hh [NN * C1];   // elu(layer1 out), fp16
__device__ float g_el1[NN * H1];
__device__ float g_er1[NN * H1];
__device__ float g_z2[NN * C2];
__device__ float g_el2[NN];
__device__ float g_er2[NN];
__device__ int   g_deg[NN];
__device__ int   g_off[NN + 1];
__device__ int   g_cur[NN];
__device__ int   g_csr[NE];
__device__ int   g_bsum[NB];

// ---------------- CSR build ----------------
__global__ void k_zero_deg() {
    int i = blockIdx.x * blockDim.x + threadIdx.x;
    if (i < NN) g_deg[i] = 0;
}

__global__ void k_hist(const int* __restrict__ dst) {
    int i = blockIdx.x * blockDim.x + threadIdx.x;
    if (i < NE) atomicAdd(&g_deg[dst[i]], 1);
}

__global__ void k_scanA() {
    __shared__ int sd[256];
    int t = threadIdx.x;
    int i = blockIdx.x * 256 + t;
    sd[t] = (i < NN) ? g_deg[i] : 0;
    __syncthreads();
    for (int off = 128; off > 0; off >>= 1) {
        if (t < off) sd[t] += sd[t + off];
        __syncthreads();
    }
    if (t == 0) g_bsum[blockIdx.x] = sd[0];
}

__global__ void k_scanB() {
    __shared__ int sd[256];
    int t = threadIdx.x;
    int v = (t < NB) ? g_bsum[t] : 0;
    sd[t] = v;
    __syncthreads();
    for (int off = 1; off < 256; off <<= 1) {
        int u = 0;
        if (t >= off) u = sd[t - off];
        __syncthreads();
        if (t >= off) sd[t] += u;
        __syncthreads();
    }
    if (t < NB) g_bsum[t] = sd[t] - v;
    if (t == 255) g_off[NN] = sd[255];
}

__global__ void k_scanC() {
    __shared__ int sd[256];
    int t = threadIdx.x;
    int i = blockIdx.x * 256 + t;
    int v = (i < NN) ? g_deg[i] : 0;
    sd[t] = v;
    __syncthreads();
    for (int off = 1; off < 256; off <<= 1) {
        int u = 0;
        if (t >= off) u = sd[t - off];
        __syncthreads();
        if (t >= off) sd[t] += u;
        __syncthreads();
    }
    if (i < NN) {
        int ex = g_bsum[blockIdx.x] + sd[t] - v;
        g_off[i] = ex;
        g_cur[i] = ex;
    }
}

__global__ void k_scatter(const int* __restrict__ src, const int* __restrict__ dst) {
    int i = blockIdx.x * blockDim.x + threadIdx.x;
    if (i < NE) {
        int pos = atomicAdd(&g_cur[dst[i]], 1);
        g_csr[pos] = src[i];
    }
}

__device__ __forceinline__ float lrelu(float x) { return x > 0.f ? x : 0.2f * x; }
__device__ __forceinline__ float elu(float x)  { return x > 0.f ? x : __expf(x) - 1.f; }

__device__ __forceinline__ void mma16816(float* d, const unsigned* a, const unsigned* b) {
    asm volatile(
        "mma.sync.aligned.m16n8k16.row.col.f32.f16.f16.f32 "
        "{%0,%1,%2,%3}, {%4,%5,%6,%7}, {%8,%9}, {%0,%1,%2,%3};"
        : "+f"(d[0]), "+f"(d[1]), "+f"(d[2]), "+f"(d[3])
        : "r"(a[0]), "r"(a[1]), "r"(a[2]), "r"(a[3]), "r"(b[0]), "r"(b[1]));
}

// ---------------- GEMM1 (tensor core) + fused el1/er1 ----------------
#define AS1 72
#define BS1 76
__global__ __launch_bounds__(256) void k_gemm1(
        const float* __restrict__ A, const float* __restrict__ B,
        const float* __restrict__ al1, const float* __restrict__ ar1) {
    __shared__ __align__(16) __half As[64 * AS1];
    __shared__ __align__(16) __half Bs[256 * BS1];
    int by = blockIdx.x;
    int tid = threadIdx.x;
    int wid = tid >> 5, lane = tid & 31;
    int g = lane >> 2, t4 = lane & 3;
    int warp_m = wid >> 2, warp_n = wid & 3;
    int rowbase = warp_m * 32;
    int colbase = warp_n * 64;

    float d[2][8][4];
#pragma unroll
    for (int mt = 0; mt < 2; mt++)
#pragma unroll
        for (int nt = 0; nt < 8; nt++)
#pragma unroll
            for (int q = 0; q < 4; q++) d[mt][nt][q] = 0.f;

    for (int k0 = 0; k0 < 128; k0 += 64) {
#pragma unroll
        for (int q = 0; q < 4; q++) {
            int li = tid + q * 256;
            int row = li >> 4;
            int c4 = (li & 15) * 4;
            int grow = by * 64 + row;
            float4 av = make_float4(0.f, 0.f, 0.f, 0.f);
            if (grow < NN) av = *(const float4*)(A + grow * 128 + k0 + c4);
            __half2 h0 = __floats2half2_rn(av.x, av.y);
            __half2 h1 = __floats2half2_rn(av.z, av.w);
            *(__half2*)&As[row * AS1 + c4] = h0;
            *(__half2*)&As[row * AS1 + c4 + 2] = h1;
        }
#pragma unroll
        for (int q = 0; q < 16; q++) {
            int li = tid + q * 256;
            int k = li >> 6;
            int n = (li & 63) * 4;
            float4 bv = *(const float4*)(B + (k0 + k) * 256 + n);
            Bs[(n + 0) * BS1 + k] = __float2half_rn(bv.x);
            Bs[(n + 1) * BS1 + k] = __float2half_rn(bv.y);
            Bs[(n + 2) * BS1 + k] = __float2half_rn(bv.z);
            Bs[(n + 3) * BS1 + k] = __float2half_rn(bv.w);
        }
        __syncthreads();
#pragma unroll
        for (int ks = 0; ks < 4; ks++) {
            unsigned a[2][4];
#pragma unroll
            for (int mt = 0; mt < 2; mt++) {
                const __half* ap = &As[(rowbase + mt * 16 + g) * AS1 + ks * 16 + t4 * 2];
                const __half* ap8 = ap + 8 * AS1;
                a[mt][0] = *(const unsigned*)ap;
                a[mt][1] = *(const unsigned*)ap8;
                a[mt][2] = *(const unsigned*)(ap + 8);
                a[mt][3] = *(const unsigned*)(ap8 + 8);
            }
            unsigned b[8][2];
#pragma unroll
            for (int nt = 0; nt < 8; nt++) {
                const __half* bp = &Bs[(colbase + nt * 8 + g) * BS1 + ks * 16 + t4 * 2];
                b[nt][0] = *(const unsigned*)bp;
                b[nt][1] = *(const unsigned*)(bp + 8);
            }
#pragma unroll
            for (int mt = 0; mt < 2; mt++)
#pragma unroll
                for (int nt = 0; nt < 8; nt++) mma16816(d[mt][nt], a[mt], b[nt]);
        }
        __syncthreads();
    }

    float alv[8][2], arv[8][2];
#pragma unroll
    for (int nt = 0; nt < 8; nt++) {
        int c = colbase + nt * 8 + t4 * 2;
        alv[nt][0] = __ldg(al1 + c);     alv[nt][1] = __ldg(al1 + c + 1);
        arv[nt][0] = __ldg(ar1 + c);     arv[nt][1] = __ldg(ar1 + c + 1);
    }
#pragma unroll
    for (int mt = 0; mt < 2; mt++) {
#pragma unroll
        for (int hf = 0; hf < 2; hf++) {
            int row = by * 64 + rowbase + mt * 16 + g + hf * 8;
            float p0l = 0.f, p0r = 0.f, p1l = 0.f, p1r = 0.f;
#pragma unroll
            for (int nt = 0; nt < 8; nt++) {
                float v0 = d[mt][nt][hf * 2 + 0];
                float v1 = d[mt][nt][hf * 2 + 1];
                float pl = v0 * alv[nt][0] + v1 * alv[nt][1];
                float pr = v0 * arv[nt][0] + v1 * arv[nt][1];
                if (nt < 4) { p0l += pl; p0r += pr; }
                else        { p1l += pl; p1r += pr; }
            }
            p0l += __shfl_xor_sync(0xffffffffu, p0l, 1);
            p0r += __shfl_xor_sync(0xffffffffu, p0r, 1);
            p1l += __shfl_xor_sync(0xffffffffu, p1l, 1);
            p1r += __shfl_xor_sync(0xffffffffu, p1r, 1);
            p0l += __shfl_xor_sync(0xffffffffu, p0l, 2);
            p0r += __shfl_xor_sync(0xffffffffu, p0r, 2);
            p1l += __shfl_xor_sync(0xffffffffu, p1l, 2);
            p1r += __shfl_xor_sync(0xffffffffu, p1r, 2);
            if (row < NN) {
#pragma unroll
                for (int nt = 0; nt < 8; nt++) {
                    __half2 hv = __floats2half2_rn(d[mt][nt][hf * 2], d[mt][nt][hf * 2 + 1]);
                    *(__half2*)(g_z1h + row * 256 + colbase + nt * 8 + t4 * 2) = hv;
                }
                if (t4 == 0) {
                    int h = warp_n * 2;
                    g_el1[row * 8 + h]     = p0l;
                    g_er1[row * 8 + h]     = p0r;
                    g_el1[row * 8 + h + 1] = p1l;
                    g_er1[row * 8 + h + 1] = p1r;
                }
            }
        }
    }
}

// ---------------- layer1 aggregation: 1 warp/node, uint4 fp16 gather, unroll-8 ----------------
__global__ void k_agg1(const float* __restrict__ b1) {
    int n = blockIdx.x * 8 + (threadIdx.x >> 5);
    if (n >= NN) return;
    int lane = threadIdx.x & 31;
    int c0 = lane * 8;
    int h = lane >> 2;
    int beg = g_off[n], end = g_off[n + 1];
    float erd = g_er1[n * 8 + h];
    float acc[8];
#pragma unroll
    for (int q = 0; q < 8; q++) acc[q] = 0.f;
    float ds = 0.f;
    const __half* zb = g_z1h + c0;

    int j = beg;
    for (; j + 8 <= end; j += 8) {
        int s[8]; float e[8]; uint4 v[8];
#pragma unroll
        for (int q = 0; q < 8; q++) s[q] = __ldg(&g_csr[j + q]);
#pragma unroll
        for (int q = 0; q < 8; q++) e[q] = __ldg(&g_el1[s[q] * 8 + h]);
#pragma unroll
        for (int q = 0; q < 8; q++) v[q] = __ldg((const uint4*)(zb + s[q] * 256));
#pragma unroll
        for (int q = 0; q < 8; q++) {
            float x = __expf(lrelu(e[q] + erd));
            ds += x;
            const unsigned* p = &v[q].x;
#pragma unroll
            for (int r = 0; r < 4; r++) {
                float2 f = __half22float2(*(const __half2*)&p[r]);
                acc[r * 2 + 0] += x * f.x;
                acc[r * 2 + 1] += x * f.y;
            }
        }
    }
    for (; j + 4 <= end; j += 4) {
        int s[4]; float e[4]; uint4 v[4];
#pragma unroll
        for (int q = 0; q < 4; q++) s[q] = __ldg(&g_csr[j + q]);
#pragma unroll
        for (int q = 0; q < 4; q++) e[q] = __ldg(&g_el1[s[q] * 8 + h]);
#pragma unroll
        for (int q = 0; q < 4; q++) v[q] = __ldg((const uint4*)(zb + s[q] * 256));
#pragma unroll
        for (int q = 0; q < 4; q++) {
            float x = __expf(lrelu(e[q] + erd));
            ds += x;
            const unsigned* p = &v[q].x;
#pragma unroll
            for (int r = 0; r < 4; r++) {
                float2 f = __half22float2(*(const __half2*)&p[r]);
                acc[r * 2 + 0] += x * f.x;
                acc[r * 2 + 1] += x * f.y;
            }
        }
    }
    for (; j < end; j++) {
        int s = __ldg(&g_csr[j]);
        float x = __expf(lrelu(__ldg(&g_el1[s * 8 + h]) + erd));
        uint4 v = __ldg((const uint4*)(zb + s * 256));
        ds += x;
        const unsigned* p = &v.x;
#pragma unroll
        for (int r = 0; r < 4; r++) {
            float2 f = __half22float2(*(const __half2*)&p[r]);
            acc[r * 2 + 0] += x * f.x;
            acc[r * 2 + 1] += x * f.y;
        }
    }
    float inv = (end > beg) ? 1.f / ds : 0.f;
    float4 bb0 = *(const float4*)(b1 + c0);
    float4 bb1 = *(const float4*)(b1 + c0 + 4);
    float o[8];
    o[0] = elu(acc[0] * inv + bb0.x); o[1] = elu(acc[1] * inv + bb0.y);
    o[2] = elu(acc[2] * inv + bb0.z); o[3] = elu(acc[3] * inv + bb0.w);
    o[4] = elu(acc[4] * inv + bb1.x); o[5] = elu(acc[5] * inv + bb1.y);
    o[6] = elu(acc[6] * inv + bb1.z); o[7] = elu(acc[7] * inv + bb1.w);
    uint4 pk;
    __half2 q0 = __floats2half2_rn(o[0], o[1]);
    __half2 q1 = __floats2half2_rn(o[2], o[3]);
    __half2 q2 = __floats2half2_rn(o[4], o[5]);
    __half2 q3 = __floats2half2_rn(o[6], o[7]);
    pk.x = *(unsigned*)&q0; pk.y = *(unsigned*)&q1;
    pk.z = *(unsigned*)&q2; pk.w = *(unsigned*)&q3;
    *(uint4*)(g_hh + n * 256 + c0) = pk;
}

// ---------------- GEMM2 (tensor core) + fused el2/er2 ----------------
#define AS2 72
#define BS2 76
__global__ __launch_bounds__(256) void k_gemm2(
        const float* __restrict__ W2,
        const float* __restrict__ al2, const float* __restrict__ ar2) {
    __shared__ __align__(16) __half As[128 * AS2];
    __shared__ __align__(16) __half Bs[40 * BS2];
    int by = blockIdx.x;
    int tid = threadIdx.x;
    int wid = tid >> 5, lane = tid & 31;
    int g = lane >> 2, t4 = lane & 3;

    float d[5][4];
#pragma unroll
    for (int nt = 0; nt < 5; nt++)
#pragma unroll
        for (int q = 0; q < 4; q++) d[nt][q] = 0.f;

    for (int k0 = 0; k0 < 256; k0 += 64) {
#pragma unroll
        for (int q = 0; q < 4; q++) {
            int li = tid + q * 256;
            int row = li >> 3;
            int c8 = (li & 7) * 8;
            int grow = by * 128 + row;
            uint4 v = make_uint4(0, 0, 0, 0);
            if (grow < NN) v = *(const uint4*)(g_hh + grow * 256 + k0 + c8);
            *(uint4*)&As[row * AS2 + c8] = v;
        }
        for (int li = tid; li < 640; li += 256) {
            int k = li / 10;
            int n = (li % 10) * 4;
            float4 bv = *(const float4*)(W2 + (k0 + k) * 40 + n);
            Bs[(n + 0) * BS2 + k] = __float2half_rn(bv.x);
            Bs[(n + 1) * BS2 + k] = __float2half_rn(bv.y);
            Bs[(n + 2) * BS2 + k] = __float2half_rn(bv.z);
            Bs[(n + 3) * BS2 + k] = __float2half_rn(bv.w);
        }
        __syncthreads();
#pragma unroll
        for (int ks = 0; ks < 4; ks++) {
            unsigned a[4];
            const __half* ap = &As[(wid * 16 + g) * AS2 + ks * 16 + t4 * 2];
            const __half* ap8 = ap + 8 * AS2;
            a[0] = *(const unsigned*)ap;
            a[1] = *(const unsigned*)ap8;
            a[2] = *(const unsigned*)(ap + 8);
            a[3] = *(const unsigned*)(ap8 + 8);
            unsigned b[5][2];
#pragma unroll
            for (int nt = 0; nt < 5; nt++) {
                const __half* bp = &Bs[(nt * 8 + g) * BS2 + ks * 16 + t4 * 2];
                b[nt][0] = *(const unsigned*)bp;
                b[nt][1] = *(const unsigned*)(bp + 8);
            }
#pragma unroll
            for (int nt = 0; nt < 5; nt++) mma16816(d[nt], a, b[nt]);
        }
        __syncthreads();
    }

    float alv[5][2], arv[5][2];
#pragma unroll
    for (int nt = 0; nt < 5; nt++) {
        int c = nt * 8 + t4 * 2;
        alv[nt][0] = __ldg(al2 + c);     alv[nt][1] = __ldg(al2 + c + 1);
        arv[nt][0] = __ldg(ar2 + c);     arv[nt][1] = __ldg(ar2 + c + 1);
    }
#pragma unroll
    for (int hf = 0; hf < 2; hf++) {
        int row = by * 128 + wid * 16 + g + hf * 8;
        float pl = 0.f, pr = 0.f;
#pragma unroll
        for (int nt = 0; nt < 5; nt++) {
            float v0 = d[nt][hf * 2 + 0];
            float v1 = d[nt][hf * 2 + 1];
            pl += v0 * alv[nt][0] + v1 * alv[nt][1];
            pr += v0 * arv[nt][0] + v1 * arv[nt][1];
        }
        pl += __shfl_xor_sync(0xffffffffu, pl, 1);
        pr += __shfl_xor_sync(0xffffffffu, pr, 1);
        pl += __shfl_xor_sync(0xffffffffu, pl, 2);
        pr += __shfl_xor_sync(0xffffffffu, pr, 2);
        if (row < NN) {
#pragma unroll
            for (int nt = 0; nt < 5; nt++) {
                float2 fv = make_float2(d[nt][hf * 2], d[nt][hf * 2 + 1]);
                *(float2*)(g_z2 + row * 40 + nt * 8 + t4 * 2) = fv;
            }
            if (t4 == 0) {
                g_el2[row] = pl;
                g_er2[row] = pr;
            }
        }
    }
}

// ---------------- layer2 aggregation (warp/node, unroll-4) ----------------
__global__ void k_agg2(const float* __restrict__ b2, float* __restrict__ out) {
    int n = blockIdx.x * 8 + (threadIdx.x >> 5);
    if (n >= NN) return;
    int lane = threadIdx.x & 31;
    int beg = g_off[n], end = g_off[n + 1];
    float erd = g_er2[n];
    float acc0 = 0.f, acc1 = 0.f, ds = 0.f;
    int j = beg;
    for (; j + 4 <= end; j += 4) {
        int s0 = __ldg(&g_csr[j + 0]);
        int s1 = __ldg(&g_csr[j + 1]);
        int s2 = __ldg(&g_csr[j + 2]);
        int s3 = __ldg(&g_csr[j + 3]);
        float e0 = __ldg(&g_el2[s0]);
        float e1 = __ldg(&g_el2[s1]);
        float e2 = __ldg(&g_el2[s2]);
        float e3 = __ldg(&g_el2[s3]);
        float v0 = __ldg(&g_z2[s0 * 40 + lane]);
        float v1 = __ldg(&g_z2[s1 * 40 + lane]);
        float v2 = __ldg(&g_z2[s2 * 40 + lane]);
        float v3 = __ldg(&g_z2[s3 * 40 + lane]);
        float u0 = 0.f, u1 = 0.f, u2 = 0.f, u3 = 0.f;
        if (lane < 8) {
            u0 = __ldg(&g_z2[s0 * 40 + 32 + lane]);
            u1 = __ldg(&g_z2[s1 * 40 + 32 + lane]);
            u2 = __ldg(&g_z2[s2 * 40 + 32 + lane]);
            u3 = __ldg(&g_z2[s3 * 40 + 32 + lane]);
        }
        float x0 = __expf(lrelu(e0 + erd));
        float x1 = __expf(lrelu(e1 + erd));
        float x2 = __expf(lrelu(e2 + erd));
        float x3 = __expf(lrelu(e3 + erd));
        ds += (x0 + x1) + (x2 + x3);
        acc0 += x0 * v0 + x1 * v1 + x2 * v2 + x3 * v3;
        acc1 += x0 * u0 + x1 * u1 + x2 * u2 + x3 * u3;
    }
    for (; j < end; j++) {
        int s = __ldg(&g_csr[j]);
        float x = __expf(lrelu(__ldg(&g_el2[s]) + erd));
        ds += x;
        acc0 += x * __ldg(&g_z2[s * 40 + lane]);
        if (lane < 8) acc1 += x * __ldg(&g_z2[s * 40 + 32 + lane]);
    }
    float inv = (end > beg) ? 1.f / ds : 0.f;
    out[n * 40 + lane] = acc0 * inv + __ldg(b2 + lane);
    if (lane < 8) out[n * 40 + 32 + lane] = acc1 * inv + __ldg(b2 + 32 + lane);
}

// ---------------- launch ----------------
static cudaStream_t s_side = 0;
static cudaEvent_t  s_evFork = 0, s_evJoin = 0;

extern "C" void kernel_launch(void* const* d_in, const int* in_sizes, int n_in,
                              void* d_out, int out_size) {
    const float* feat = (const float*)d_in[0];
    const int*   src  = (const int*)d_in[1];
    const int*   dst  = (const int*)d_in[2];
    const float* W1   = (const float*)d_in[3];
    const float* al1  = (const float*)d_in[4];
    const float* ar1  = (const float*)d_in[5];
    const float* b1   = (const float*)d_in[6];
    const float* W2   = (const float*)d_in[7];
    const float* al2  = (const float*)d_in[8];
    const float* ar2  = (const float*)d_in[9];
    const float* b2   = (const float*)d_in[10];
    float* out = (float*)d_out;

    if (s_side == 0) {
        cudaStreamCreateWithFlags(&s_side, cudaStreamNonBlocking);
        cudaEventCreateWithFlags(&s_evFork, cudaEventDisableTiming);
        cudaEventCreateWithFlags(&s_evJoin, cudaEventDisableTiming);
    }

    // fork: gemm1 (independent of CSR) runs on the side stream
    cudaEventRecord(s_evFork, 0);
    cudaStreamWaitEvent(s_side, s_evFork, 0);
    k_gemm1<<<(NN + 63) / 64, 256, 0, s_side>>>(feat, W1, al1, ar1);
    cudaEventRecord(s_evJoin, s_side);

    // CSR chain on the main stream, concurrent with gemm1
    k_zero_deg<<<(NN + 255) / 256, 256>>>();
    k_hist<<<(NE + 255) / 256, 256>>>(dst);
    k_scanA<<<NB, 256>>>();
    k_scanB<<<1, 256>>>();
    k_scanC<<<NB, 256>>>();
    k_scatter<<<(NE + 255) / 256, 256>>>(src, dst);

    // join: agg1 needs both CSR and gemm1 outputs
    cudaStreamWaitEvent(0, s_evJoin, 0);
    k_agg1<<<(NN + 7) / 8, 256>>>(b1);

    k_gemm2<<<(NN + 127) / 128, 256>>>(W2, al2, ar2);
    k_agg2<<<(NN + 7) / 8, 256>>>(b2, out);
}